// round 3
// baseline (speedup 1.0000x reference)
#include <cuda_runtime.h>

#define NPTS 32768
#define BB 8
#define CC 32
#define NBLK 2
#define KIN 22
#define NCAT 40

typedef unsigned long long ull;

// ---------------- scratch (device globals; no allocations allowed) ----------------
__device__ float    g_bufA[(size_t)BB * 256 * NPTS];
__device__ float    g_buf64[(size_t)BB * 64 * NPTS];
__device__ float    g_FB[(size_t)BB * 128 * NPTS];
__device__ float    g_bufT[(size_t)BB * 128 * NPTS];
__device__ float    g_bufC[(size_t)BB * 32 * NPTS];
__device__ ull      g_wpack[245760];            // packed dup2 weights, k-major
__device__ unsigned g_segf[BB * 128 * CC];
__device__ unsigned g_segc[BB * 32 * CC];
__device__ float    g_cfm[BB * 128 * CC];
__device__ float    g_net[BB * 128];

// ---------------- helpers ----------------
__device__ __forceinline__ unsigned f2o(float f) {
    unsigned u = __float_as_uint(f);
    return (u & 0x80000000u) ? ~u : (u | 0x80000000u);
}
__device__ __forceinline__ float o2f(unsigned u) {
    u = (u & 0x80000000u) ? (u & 0x7fffffffu) : ~u;
    return __uint_as_float(u);
}
__device__ __forceinline__ ull ffma2(ull a, ull b, ull c) {
    ull d;
    asm("fma.rn.f32x2 %0, %1, %2, %3;" : "=l"(d) : "l"(a), "l"(b), "l"(c));
    return d;
}
__device__ __forceinline__ ull dup2(float a) {
    ull d;
    asm("mov.b64 %0, {%1, %1};" : "=l"(d) : "f"(a));
    return d;
}
__device__ __forceinline__ float2 unpack2(ull v) {
    float2 r;
    asm("mov.b64 {%0, %1}, %2;" : "=f"(r.x), "=f"(r.y) : "l"(v));
    return r;
}

// ---------------- weight packing: W[Cout,Cin] -> Wp[c*Cout+o] = dup2(W[o,c]) ----------------
__global__ void pack_kernel(const float* __restrict__ W, ull* __restrict__ dst,
                            int Cout, int Cin)
{
    int i = blockIdx.x * 256 + threadIdx.x;
    if (i < Cout * Cin) {
        int c = i / Cout, o = i % Cout;
        dst[i] = dup2(W[(size_t)o * Cin + c]);
    }
}

// ---------------- input layer: x(B,N,22) -> relu(w_in x + b) (B,256,N) ----------------
__global__ __launch_bounds__(256) void input_kernel(
    const float* __restrict__ x, const float* __restrict__ w_in,
    const float* __restrict__ b_in, float* __restrict__ out)
{
    __shared__ float xs[KIN][128];
    __shared__ float ws[KIN][256];
    const int tid = threadIdx.x;
    const int b = blockIdx.y;
    const int n0 = blockIdx.x * 128;

    const float* gx = x + ((size_t)b * NPTS + n0) * KIN;
    for (int i = tid; i < 128 * KIN; i += 256) xs[i % KIN][i / KIN] = gx[i];
    for (int i = tid; i < 256 * KIN; i += 256) ws[i % KIN][i / KIN] = w_in[i];
    __syncthreads();

    const int tx = tid & 15;
    const int ty = tid >> 4;
    for (int om = 0; om < 256; om += 128) {
        float acc[8][8];
        #pragma unroll
        for (int m = 0; m < 8; m++)
            #pragma unroll
            for (int j = 0; j < 8; j++) acc[m][j] = 0.f;
        for (int k = 0; k < KIN; k++) {
            float a[8], bb[8];
            #pragma unroll
            for (int m = 0; m < 8; m++) a[m] = ws[k][om + ty * 8 + m];
            #pragma unroll
            for (int j = 0; j < 8; j++) bb[j] = xs[k][tx * 8 + j];
            #pragma unroll
            for (int m = 0; m < 8; m++)
                #pragma unroll
                for (int j = 0; j < 8; j++) acc[m][j] = fmaf(a[m], bb[j], acc[m][j]);
        }
        #pragma unroll
        for (int m = 0; m < 8; m++) {
            const int o = om + ty * 8 + m;
            const float bv = b_in[o];
            float r[8];
            #pragma unroll
            for (int j = 0; j < 8; j++) r[j] = fmaxf(acc[m][j] + bv, 0.f);
            float* go = out + ((size_t)b * 256 + o) * NPTS + n0 + tx * 8;
            *(float4*)go = make_float4(r[0], r[1], r[2], r[3]);
            *(float4*)(go + 4) = make_float4(r[4], r[5], r[6], r[7]);
        }
    }
}

// ---------------- conv2: out[b,o,n] = relu(sum_c W[o,c] in[b,c,n] + bias[o]) ----------------
// BM outputs per CTA-y, PTS points per CTA-x; thread tile TM outs x 8 pts (f32x2).
// Weights come pre-packed (k-major, dup2'd) -> broadcast LDS.128, no dup in hot loop.
template <int BM, int TM, int PTS>
__global__ __launch_bounds__(256, 2) void conv2_kernel(
    const float* __restrict__ in, size_t ibs,
    const ull* __restrict__ Wp, const float* __restrict__ bias,
    float* __restrict__ out, size_t obs, int Cin, int Cout)
{
    constexpr int TX = PTS / 8;
    constexpr int TY = 256 / TX;
    static_assert(TY * TM == BM, "tile mismatch");

    extern __shared__ char smem_raw[];
    float* INs = (float*)smem_raw;                       // [32][PTS]
    ull*   Ws2 = (ull*)(smem_raw + 32 * PTS * 4);        // [32][BM]

    const int tid = threadIdx.x;
    const int b = blockIdx.z;
    const int n0 = blockIdx.x * PTS;
    const int om0 = blockIdx.y * BM;
    const int tx = tid % TX;
    const int ty = tid / TX;

    ull acc[TM][4];
    #pragma unroll
    for (int m = 0; m < TM; m++)
        #pragma unroll
        for (int j = 0; j < 4; j++) acc[m][j] = 0ull;

    for (int kc = 0; kc < Cin; kc += 32) {
        __syncthreads();
        // stage inputs: 32 channel-rows x PTS points
        const float* gin = in + (size_t)b * ibs + (size_t)kc * NPTS + n0;
        constexpr int NV = 32 * PTS / 4;        // float4 count
        #pragma unroll
        for (int t = 0; t < NV / 256; t++) {
            const int idx = tid + t * 256;
            const int row = idx / (PTS / 4), c4 = idx % (PTS / 4);
            float4 v = *(const float4*)(gin + (size_t)row * NPTS + c4 * 4);
            *(float4*)(INs + row * PTS + c4 * 4) = v;
        }
        // stage packed weights: [k][o] ull, coalesced global + conflict-free STS
        const ull* gw = Wp + (size_t)kc * Cout + om0;
        constexpr int NW2 = 32 * BM / 2;        // ulonglong2 count
        #pragma unroll
        for (int t = 0; t < (NW2 + 255) / 256; t++) {
            const int idx = tid + t * 256;
            if (NW2 % 256 == 0 || idx < NW2) {
                const int e = idx * 2;
                const int k = e / BM, o = e % BM;
                ulonglong2 v = *(const ulonglong2*)(gw + (size_t)k * Cout + o);
                *(ulonglong2*)(Ws2 + k * BM + o) = v;
            }
        }
        __syncthreads();

        #pragma unroll
        for (int k = 0; k < 32; k++) {
            const ulonglong2* ap = (const ulonglong2*)(Ws2 + k * BM + ty * TM);
            ull a2[TM];
            #pragma unroll
            for (int j = 0; j < TM / 2; j++) {
                ulonglong2 av = ap[j];
                a2[2 * j] = av.x; a2[2 * j + 1] = av.y;
            }
            const ulonglong2* bp = (const ulonglong2*)(INs + k * PTS + tx * 8);
            ulonglong2 bv0 = bp[0], bv1 = bp[1];
            ull b2[4] = {bv0.x, bv0.y, bv1.x, bv1.y};
            #pragma unroll
            for (int m = 0; m < TM; m++)
                #pragma unroll
                for (int j = 0; j < 4; j++) acc[m][j] = ffma2(a2[m], b2[j], acc[m][j]);
        }
    }

    #pragma unroll
    for (int m = 0; m < TM; m++) {
        const int o = om0 + ty * TM + m;
        const float bv = bias[o];
        float r[8];
        #pragma unroll
        for (int j = 0; j < 4; j++) {
            float2 p = unpack2(acc[m][j]);
            r[2 * j]     = fmaxf(p.x + bv, 0.f);
            r[2 * j + 1] = fmaxf(p.y + bv, 0.f);
        }
        float* go = out + (size_t)b * obs + (size_t)o * NPTS + n0 + tx * 8;
        *(float4*)go = make_float4(r[0], r[1], r[2], r[3]);
        *(float4*)(go + 4) = make_float4(r[4], r[5], r[6], r[7]);
    }
}

// ---------------- fill ordered-uint buffer ----------------
__global__ void fill_kernel(unsigned* p, unsigned v, int n) {
    int i = blockIdx.x * 256 + threadIdx.x;
    if (i < n) p[i] = v;
}

// ---------------- segmented max ----------------
__global__ __launch_bounds__(256) void segmax_kernel(
    const float* __restrict__ in, size_t ibs, int CH,
    const int* __restrict__ idx, unsigned* __restrict__ segout)
{
    __shared__ unsigned s[CC * 128];
    __shared__ int cl[1024];
    const int tid = threadIdx.x;
    const int b = blockIdx.y;
    const int n0 = blockIdx.x * 1024;
    const unsigned NEG = 0x3D37FFFFu;  // f2o(-100.0f)

    for (int i = tid; i < CC * CH; i += 256) s[i] = NEG;
    for (int i = tid; i < 1024; i += 256) cl[i] = idx[(size_t)b * NPTS + n0 + i];
    __syncthreads();

    const int lane = tid & 31, w = tid >> 5;
    for (int ch = w; ch < CH; ch += 8) {
        const float* row = in + (size_t)b * ibs + (size_t)ch * NPTS + n0;
        for (int p = lane; p < 1024; p += 32)
            atomicMax(&s[cl[p] * CH + ch], f2o(row[p]));
    }
    __syncthreads();
    for (int i = tid; i < CC * CH; i += 256) {
        const int c = i / CH, ch = i % CH;
        atomicMax(&segout[((size_t)b * CH + ch) * CC + c], s[i]);
    }
}

// ---------------- pooling math ----------------
__global__ __launch_bounds__(256) void pool_kernel(
    const unsigned* __restrict__ segf, const unsigned* __restrict__ segc,
    float* __restrict__ cfm)
{
    const int b = blockIdx.x;
    const int tid = threadIdx.x;
    __shared__ float cm[CC][CC];
    __shared__ float inv[CC];
    __shared__ float M[CC][CC];

    for (int i = tid; i < CC * CC; i += 256) {
        const int c = i / CC, j = i % CC;
        cm[c][j] = o2f(segc[((size_t)b * CC + j) * CC + c]);
    }
    __syncthreads();
    if (tid < CC) {
        float ss = 0.f;
        for (int j = 0; j < CC; j++) ss += cm[tid][j] * cm[tid][j];
        inv[tid] = 1.f / fmaxf(sqrtf(ss), 1e-12f);
    }
    __syncthreads();
    for (int i = tid; i < CC * CC; i += 256) {
        const int c1 = i / CC, c2 = i % CC;
        float ss = 0.f;
        for (int j = 0; j < CC; j++) ss += cm[c1][j] * cm[c2][j];
        M[c1][c2] = ss * inv[c1] * inv[c2];
    }
    __syncthreads();
    for (int i = tid; i < 128 * CC; i += 256) {
        const int ch = i / CC, c2 = i % CC;
        const unsigned* fr = segf + ((size_t)b * 128 + ch) * CC;
        float ss = 0.f;
        for (int c1 = 0; c1 < CC; c1++) ss += o2f(fr[c1]) * M[c1][c2];
        cfm[((size_t)b * 128 + ch) * CC + c2] = ss;
    }
}

// ---------------- gather pooled values into concat channels 128..255 ----------------
__global__ __launch_bounds__(256) void gather_kernel(
    const float* __restrict__ cfm, const int* __restrict__ idx,
    float* __restrict__ outA)
{
    __shared__ float cfs[128 * CC];
    const int tid = threadIdx.x;
    const int b = blockIdx.y;
    const int n0 = blockIdx.x * 1024;
    for (int i = tid; i < 128 * CC; i += 256) cfs[i] = cfm[(size_t)b * 128 * CC + i];
    __syncthreads();
    for (int j = tid; j < 1024; j += 256) {
        const int n = n0 + j;
        const int c = idx[(size_t)b * NPTS + n];
        float* dst = outA + ((size_t)b * 256 + 128) * NPTS + n;
        #pragma unroll 4
        for (int ch = 0; ch < 128; ch++)
            dst[(size_t)ch * NPTS] = cfs[ch * CC + c];
    }
}

// ---------------- row max ----------------
__global__ __launch_bounds__(256) void rowmax_kernel(const float* __restrict__ in, float* __restrict__ net)
{
    const int ch = blockIdx.x, b = blockIdx.y, tid = threadIdx.x;
    const float* row = in + ((size_t)b * 128 + ch) * NPTS;
    float m = -1e30f;
    for (int n = tid; n < NPTS; n += 256) m = fmaxf(m, row[n]);
    __shared__ float s[256];
    s[tid] = m;
    __syncthreads();
    for (int off = 128; off; off >>= 1) {
        if (tid < off) s[tid] = fmaxf(s[tid], s[tid + off]);
        __syncthreads();
    }
    if (tid == 0) net[b * 128 + ch] = s[0];
}

// ---------------- head MLP ----------------
__global__ __launch_bounds__(256) void mlp_kernel(
    const float* __restrict__ net,
    const float* __restrict__ dw1, const float* __restrict__ db1,
    const float* __restrict__ dw2, const float* __restrict__ db2,
    const float* __restrict__ dw3, const float* __restrict__ db3,
    float* __restrict__ out)
{
    const int tid = threadIdx.x;
    __shared__ float ns[BB][128];
    __shared__ float h1[BB][256];
    __shared__ float h2[BB][256];
    for (int i = tid; i < BB * 128; i += 256) ns[i / 128][i % 128] = net[i];
    __syncthreads();
    {
        const int j = tid;
        for (int b = 0; b < BB; b++) {
            float acc = db1[j];
            for (int i = 0; i < 128; i++) acc = fmaf(ns[b][i], dw1[i * 256 + j], acc);
            h1[b][j] = (acc >= 0.f) ? acc : 0.2f * acc;
        }
    }
    __syncthreads();
    {
        const int j = tid;
        for (int b = 0; b < BB; b++) {
            float acc = db2[j];
            for (int i = 0; i < 256; i++) acc = fmaf(h1[b][i], dw2[i * 256 + j], acc);
            h2[b][j] = (acc >= 0.f) ? acc : 0.2f * acc;
        }
    }
    __syncthreads();
    if (tid < NCAT) {
        for (int b = 0; b < BB; b++) {
            float acc = db3[tid];
            for (int i = 0; i < 256; i++) acc = fmaf(h2[b][i], dw3[i * NCAT + tid], acc);
            out[b * NCAT + tid] = acc;
        }
    }
}

// ---------------- host launcher ----------------
extern "C" void kernel_launch(void* const* d_in, const int* in_sizes, int n_in,
                              void* d_out, int out_size)
{
    const float* features = (const float*)d_in[0];
    const int*   clusters = (const int*)d_in[1];
    const float* w_in  = (const float*)d_in[2];
    const float* b_in  = (const float*)d_in[3];
    const float* w1    = (const float*)d_in[4];
    const float* b1    = (const float*)d_in[5];
    const float* w2    = (const float*)d_in[6];
    const float* b2    = (const float*)d_in[7];
    const float* w3    = (const float*)d_in[8];
    const float* b3    = (const float*)d_in[9];
    const float* wc1   = (const float*)d_in[10];
    const float* bc1   = (const float*)d_in[11];
    const float* wc2   = (const float*)d_in[12];
    const float* bc2   = (const float*)d_in[13];
    const float* wc3   = (const float*)d_in[14];
    const float* bc3   = (const float*)d_in[15];
    const float* w_out1 = (const float*)d_in[16];
    const float* b_out1 = (const float*)d_in[17];
    const float* w_out2 = (const float*)d_in[18];
    const float* b_out2 = (const float*)d_in[19];
    const float* dw1 = (const float*)d_in[20];
    const float* db1 = (const float*)d_in[21];
    const float* dw2 = (const float*)d_in[22];
    const float* db2 = (const float*)d_in[23];
    const float* dw3 = (const float*)d_in[24];
    const float* db3 = (const float*)d_in[25];
    float* out = (float*)d_out;

    float *bufA, *buf64, *FB, *bufT, *bufC, *cfm, *net;
    unsigned *segf, *segc;
    ull *wp;
    cudaGetSymbolAddress((void**)&bufA, g_bufA);
    cudaGetSymbolAddress((void**)&buf64, g_buf64);
    cudaGetSymbolAddress((void**)&FB, g_FB);
    cudaGetSymbolAddress((void**)&bufT, g_bufT);
    cudaGetSymbolAddress((void**)&bufC, g_bufC);
    cudaGetSymbolAddress((void**)&wp, g_wpack);
    cudaGetSymbolAddress((void**)&segf, g_segf);
    cudaGetSymbolAddress((void**)&segc, g_segc);
    cudaGetSymbolAddress((void**)&cfm, g_cfm);
    cudaGetSymbolAddress((void**)&net, g_net);

    // dynamic smem opt-in (idempotent)
    const int SM_A = 32 * 256 * 4 + 32 * 64 * 8;   // 49152 : <64,8,256>
    const int SM_B = 32 * 128 * 4 + 32 * 128 * 8;  // 49152 : <128,8,128>
    const int SM_C = 32 * 256 * 4 + 32 * 32 * 8;   // 40960 : <32,4,256>
    cudaFuncSetAttribute(conv2_kernel<64, 8, 256>,  cudaFuncAttributeMaxDynamicSharedMemorySize, SM_A);
    cudaFuncSetAttribute(conv2_kernel<128, 8, 128>, cudaFuncAttributeMaxDynamicSharedMemorySize, SM_B);
    cudaFuncSetAttribute(conv2_kernel<32, 4, 256>,  cudaFuncAttributeMaxDynamicSharedMemorySize, SM_C);

    const size_t S256 = (size_t)256 * NPTS, S128 = (size_t)128 * NPTS;
    const size_t S64 = (size_t)64 * NPTS, S32 = (size_t)32 * NPTS;
    const unsigned NEG = 0x3D37FFFFu;

    // packed-weight arena offsets (ull units)
    const size_t OFF_W1 = 0;           // 2 x 16384
    const size_t OFF_W2 = 32768;       // 2 x  8192
    const size_t OFF_W3 = 49152;       // 2 x 16384
    const size_t OFF_WC1 = 81920;      // 2 x 16384
    const size_t OFF_WC2 = 114688;     // 2 x 32768
    const size_t OFF_WC3 = 180224;     // 2 x  8192
    const size_t OFF_WO1 = 196608;     //     32768
    const size_t OFF_WO2 = 229376;     //     16384

    // pack all weights (cheap; graph nodes, ordered on stream)
    for (int i = 0; i < NBLK; i++) {
        pack_kernel<<<(64 * 256 + 255) / 256, 256>>>(w1 + (size_t)i * 64 * 256, wp + OFF_W1 + i * 16384, 64, 256);
        pack_kernel<<<(128 * 64 + 255) / 256, 256>>>(w2 + (size_t)i * 128 * 64, wp + OFF_W2 + i * 8192, 128, 64);
        pack_kernel<<<(128 * 128 + 255) / 256, 256>>>(w3 + (size_t)i * 128 * 128, wp + OFF_W3 + i * 16384, 128, 128);
        pack_kernel<<<(128 * 128 + 255) / 256, 256>>>(wc1 + (size_t)i * 128 * 128, wp + OFF_WC1 + i * 16384, 128, 128);
        pack_kernel<<<(256 * 128 + 255) / 256, 256>>>(wc2 + (size_t)i * 256 * 128, wp + OFF_WC2 + i * 32768, 256, 128);
        pack_kernel<<<(32 * 256 + 255) / 256, 256>>>(wc3 + (size_t)i * 32 * 256, wp + OFF_WC3 + i * 8192, 32, 256);
    }
    pack_kernel<<<(128 * 256 + 255) / 256, 256>>>(w_out1, wp + OFF_WO1, 128, 256);
    pack_kernel<<<(128 * 128 + 255) / 256, 256>>>(w_out2, wp + OFF_WO2, 128, 128);

    input_kernel<<<dim3(NPTS / 128, BB), 256>>>(features, w_in, b_in, bufA);

    for (int i = 0; i < NBLK; i++) {
        const float* b1i = b1 + i * 64;
        const float* b2i = b2 + i * 128;
        const float* b3i = b3 + i * 128;
        const float* bc1i = bc1 + i * 128;
        const float* bc2i = bc2 + i * 256;
        const float* bc3i = bc3 + i * 32;
        const int* idxi = clusters + (size_t)i * BB * NPTS;

        conv2_kernel<64, 8, 256><<<dim3(NPTS / 256, 1, BB), 256, SM_A>>>(bufA, S256, wp + OFF_W1 + i * 16384, b1i, buf64, S64, 256, 64);
        conv2_kernel<128, 8, 128><<<dim3(NPTS / 128, 1, BB), 256, SM_B>>>(buf64, S64, wp + OFF_W2 + i * 8192, b2i, FB, S128, 64, 128);
        conv2_kernel<128, 8, 128><<<dim3(NPTS / 128, 1, BB), 256, SM_B>>>(FB, S128, wp + OFF_WC1 + i * 16384, bc1i, bufT, S128, 128, 128);
        conv2_kernel<128, 8, 128><<<dim3(NPTS / 128, 2, BB), 256, SM_B>>>(bufT, S128, wp + OFF_WC2 + i * 32768, bc2i, bufA, S256, 128, 256);
        conv2_kernel<32, 4, 256><<<dim3(NPTS / 256, 1, BB), 256, SM_C>>>(bufA, S256, wp + OFF_WC3 + i * 8192, bc3i, bufC, S32, 256, 32);

        fill_kernel<<<(BB * 128 * CC + 255) / 256, 256>>>(segf, NEG, BB * 128 * CC);
        fill_kernel<<<(BB * 32 * CC + 255) / 256, 256>>>(segc, NEG, BB * 32 * CC);
        segmax_kernel<<<dim3(NPTS / 1024, BB), 256>>>(FB, S128, 128, idxi, segf);
        segmax_kernel<<<dim3(NPTS / 1024, BB), 256>>>(bufC, S32, 32, idxi, segc);
        pool_kernel<<<BB, 256>>>(segf, segc, cfm);

        conv2_kernel<128, 8, 128><<<dim3(NPTS / 128, 1, BB), 256, SM_B>>>(FB, S128, wp + OFF_W3 + i * 16384, b3i, bufA, S256, 128, 128);
        gather_kernel<<<dim3(NPTS / 1024, BB), 256>>>(cfm, idxi, bufA);
    }

    conv2_kernel<128, 8, 128><<<dim3(NPTS / 128, 1, BB), 256, SM_B>>>(bufA, S256, wp + OFF_WO1, b_out1, bufT, S128, 256, 128);
    conv2_kernel<128, 8, 128><<<dim3(NPTS / 128, 1, BB), 256, SM_B>>>(bufT, S128, wp + OFF_WO2, b_out2, FB, S128, 128, 128);
    rowmax_kernel<<<dim3(128, BB), 256>>>(FB, net);
    mlp_kernel<<<1, 256>>>(net, dw1, db1, dw2, db2, dw3, db3, out);
}

// round 14
// speedup vs baseline: 1.1454x; 1.1454x over previous
#include <cuda_runtime.h>

#define NPTS 32768
#define BB 8
#define CC 32
#define NBLK 2
#define KIN 22
#define NCAT 40

typedef unsigned long long ull;

// ---------------- scratch (device globals; no allocations allowed) ----------------
__device__ float    g_bufA[(size_t)BB * 256 * NPTS];
__device__ float    g_buf64[(size_t)BB * 64 * NPTS];
__device__ float    g_FB[(size_t)BB * 128 * NPTS];
__device__ float    g_bufT[(size_t)BB * 128 * NPTS];
__device__ float    g_bufC[(size_t)BB * 32 * NPTS];
__device__ float    g_wpack[245760];            // k-major transposed weights
__device__ unsigned g_segf[BB * 128 * CC];
__device__ unsigned g_segc[BB * 32 * CC];
__device__ float    g_cfm[BB * 128 * CC];
__device__ float    g_net[BB * 128];

// ---------------- helpers ----------------
__device__ __forceinline__ unsigned f2o(float f) {
    unsigned u = __float_as_uint(f);
    return (u & 0x80000000u) ? ~u : (u | 0x80000000u);
}
__device__ __forceinline__ float o2f(unsigned u) {
    u = (u & 0x80000000u) ? (u & 0x7fffffffu) : ~u;
    return __uint_as_float(u);
}
__device__ __forceinline__ ull ffma2(ull a, ull b, ull c) {
    ull d;
    asm("fma.rn.f32x2 %0, %1, %2, %3;" : "=l"(d) : "l"(a), "l"(b), "l"(c));
    return d;
}
__device__ __forceinline__ ull dup2(float a) {
    ull d;
    asm("mov.b64 %0, {%1, %1};" : "=l"(d) : "f"(a));
    return d;
}
__device__ __forceinline__ float2 unpack2(ull v) {
    float2 r;
    asm("mov.b64 {%0, %1}, %2;" : "=f"(r.x), "=f"(r.y) : "l"(v));
    return r;
}

// ---------------- weight packing: W[Cout,Cin] -> Wk[c*Cout+o] = W[o,c] ----------------
__global__ void pack_kernel(const float* __restrict__ W, float* __restrict__ dst,
                            int Cout, int Cin)
{
    int i = blockIdx.x * 256 + threadIdx.x;
    if (i < Cout * Cin) {
        int c = i / Cout, o = i % Cout;
        dst[i] = W[(size_t)o * Cin + c];
    }
}

// ---------------- input layer: x(B,N,22) -> relu(w_in x + b) (B,256,N) ----------------
__global__ __launch_bounds__(256) void input_kernel(
    const float* __restrict__ x, const float* __restrict__ w_in,
    const float* __restrict__ b_in, float* __restrict__ out)
{
    __shared__ float xs[KIN][128];
    __shared__ float ws[KIN][256];
    const int tid = threadIdx.x;
    const int b = blockIdx.y;
    const int n0 = blockIdx.x * 128;

    const float* gx = x + ((size_t)b * NPTS + n0) * KIN;
    for (int i = tid; i < 128 * KIN; i += 256) xs[i % KIN][i / KIN] = gx[i];
    for (int i = tid; i < 256 * KIN; i += 256) ws[i % KIN][i / KIN] = w_in[i];
    __syncthreads();

    const int tx = tid & 15;
    const int ty = tid >> 4;
    for (int om = 0; om < 256; om += 128) {
        float acc[8][8];
        #pragma unroll
        for (int m = 0; m < 8; m++)
            #pragma unroll
            for (int j = 0; j < 8; j++) acc[m][j] = 0.f;
        for (int k = 0; k < KIN; k++) {
            float a[8], bb[8];
            #pragma unroll
            for (int m = 0; m < 8; m++) a[m] = ws[k][om + ty * 8 + m];
            #pragma unroll
            for (int j = 0; j < 8; j++) bb[j] = xs[k][tx * 8 + j];
            #pragma unroll
            for (int m = 0; m < 8; m++)
                #pragma unroll
                for (int j = 0; j < 8; j++) acc[m][j] = fmaf(a[m], bb[j], acc[m][j]);
        }
        #pragma unroll
        for (int m = 0; m < 8; m++) {
            const int o = om + ty * 8 + m;
            const float bv = b_in[o];
            float r[8];
            #pragma unroll
            for (int j = 0; j < 8; j++) r[j] = fmaxf(acc[m][j] + bv, 0.f);
            float* go = out + ((size_t)b * 256 + o) * NPTS + n0 + tx * 8;
            *(float4*)go = make_float4(r[0], r[1], r[2], r[3]);
            *(float4*)(go + 4) = make_float4(r[4], r[5], r[6], r[7]);
        }
    }
}

// ---------------- conv5: register-prefetch pipeline, KC=16 ----------------
// out[b,o,n] = relu(sum_c W[o,c] in[b,c,n] + bias[o])
// BM outputs per CTA-y, PTS points per CTA-x; thread tile TM outs x 8 pts (f32x2).
// Weights pre-transposed k-major [Cin][Cout]; dup2 applied at use.
// Pipeline: LDG channels of chunk c+1 into regs while computing chunk c.
// NOTE: ldg_chunk takes an ABSOLUTE CHANNEL OFFSET (R5/R7/R8 bug: passed chunk index).
template <int BM, int TM, int PTS>
__global__ __launch_bounds__(256, 2) void conv5_kernel(
    const float* __restrict__ in, size_t ibs,
    const float* __restrict__ Wk, const float* __restrict__ bias,
    float* __restrict__ out, size_t obs, int Cin, int Cout)
{
    constexpr int KC = 16;
    constexpr int TX = PTS / 8;
    constexpr int TY = 256 / TX;
    static_assert(TY * TM == BM, "tile mismatch");
    constexpr int IN_ELEMS = KC * PTS;
    constexpr int W_ELEMS  = KC * BM;
    constexpr int NV4 = IN_ELEMS / 4 / 256;     // per-thread input float4s
    constexpr int WV  = W_ELEMS / 4;            // total weight float4s
    constexpr int WV4 = (WV + 255) / 256;       // per-thread weight float4s

    __shared__ float INs[IN_ELEMS];
    __shared__ float Ws[W_ELEMS];

    const int tid = threadIdx.x;
    const int b = blockIdx.z;
    const int n0 = blockIdx.x * PTS;
    const int om0 = blockIdx.y * BM;
    const int tx = tid % TX;
    const int ty = tid / TX;

    const float* gin_base = in + (size_t)b * ibs + n0;
    const float* gw_base  = Wk + om0;

    float4 pin[NV4];
    float4 pw[WV4];

    auto ldg_chunk = [&](int ch0) {    // ch0 = absolute starting channel
        const float* gi = gin_base + (size_t)ch0 * NPTS;
        #pragma unroll
        for (int t = 0; t < NV4; t++) {
            const int idx = tid + t * 256;
            const int row = idx / (PTS / 4), c4 = idx % (PTS / 4);
            pin[t] = *(const float4*)(gi + (size_t)row * NPTS + c4 * 4);
        }
        const float* gw = gw_base + (size_t)ch0 * Cout;
        #pragma unroll
        for (int t = 0; t < WV4; t++) {
            const int idx = tid + t * 256;
            if (WV % 256 == 0 || idx < WV) {
                const int k = idx / (BM / 4), o4 = idx % (BM / 4);
                pw[t] = *(const float4*)(gw + (size_t)k * Cout + o4 * 4);
            }
        }
    };

    ldg_chunk(0);

    ull acc[TM][4];
    #pragma unroll
    for (int m = 0; m < TM; m++)
        #pragma unroll
        for (int j = 0; j < 4; j++) acc[m][j] = 0ull;

    const int nc = Cin / KC;
    for (int c = 0; c < nc; c++) {
        __syncthreads();   // previous chunk's compute done before overwrite
        #pragma unroll
        for (int t = 0; t < NV4; t++) {
            const int idx = tid + t * 256;
            const int row = idx / (PTS / 4), c4 = idx % (PTS / 4);
            *(float4*)(INs + row * PTS + c4 * 4) = pin[t];
        }
        #pragma unroll
        for (int t = 0; t < WV4; t++) {
            const int idx = tid + t * 256;
            if (WV % 256 == 0 || idx < WV) {
                const int k = idx / (BM / 4), o4 = idx % (BM / 4);
                *(float4*)(Ws + k * BM + o4 * 4) = pw[t];
            }
        }
        __syncthreads();
        if (c + 1 < nc) ldg_chunk((c + 1) * KC);   // FIX: channel offset, not chunk index

        #pragma unroll
        for (int k = 0; k < KC; k++) {
            const float4* ap = (const float4*)(Ws + k * BM + ty * TM);
            ull a2[TM];
            #pragma unroll
            for (int q = 0; q < TM / 4; q++) {
                float4 av = ap[q];
                a2[4 * q + 0] = dup2(av.x);
                a2[4 * q + 1] = dup2(av.y);
                a2[4 * q + 2] = dup2(av.z);
                a2[4 * q + 3] = dup2(av.w);
            }
            const ulonglong2* bp = (const ulonglong2*)(INs + k * PTS + tx * 8);
            ulonglong2 bv0 = bp[0], bv1 = bp[1];
            ull b2[4] = {bv0.x, bv0.y, bv1.x, bv1.y};
            #pragma unroll
            for (int m = 0; m < TM; m++)
                #pragma unroll
                for (int j = 0; j < 4; j++) acc[m][j] = ffma2(a2[m], b2[j], acc[m][j]);
        }
    }

    #pragma unroll
    for (int m = 0; m < TM; m++) {
        const int o = om0 + ty * TM + m;
        const float bv = bias[o];
        float r[8];
        #pragma unroll
        for (int j = 0; j < 4; j++) {
            float2 p = unpack2(acc[m][j]);
            r[2 * j]     = fmaxf(p.x + bv, 0.f);
            r[2 * j + 1] = fmaxf(p.y + bv, 0.f);
        }
        float* go = out + (size_t)b * obs + (size_t)o * NPTS + n0 + tx * 8;
        *(float4*)go = make_float4(r[0], r[1], r[2], r[3]);
        *(float4*)(go + 4) = make_float4(r[4], r[5], r[6], r[7]);
    }
}

// ---------------- fill ordered-uint buffer ----------------
__global__ void fill_kernel(unsigned* p, unsigned v, int n) {
    int i = blockIdx.x * 256 + threadIdx.x;
    if (i < n) p[i] = v;
}

// ---------------- segmented max ----------------
__global__ __launch_bounds__(256) void segmax_kernel(
    const float* __restrict__ in, size_t ibs, int CH,
    const int* __restrict__ idx, unsigned* __restrict__ segout)
{
    __shared__ unsigned s[CC * 128];
    __shared__ int cl[1024];
    const int tid = threadIdx.x;
    const int b = blockIdx.y;
    const int n0 = blockIdx.x * 1024;
    const unsigned NEG = 0x3D37FFFFu;  // f2o(-100.0f)

    for (int i = tid; i < CC * CH; i += 256) s[i] = NEG;
    for (int i = tid; i < 1024; i += 256) cl[i] = idx[(size_t)b * NPTS + n0 + i];
    __syncthreads();

    const int lane = tid & 31, w = tid >> 5;
    for (int ch = w; ch < CH; ch += 8) {
        const float* row = in + (size_t)b * ibs + (size_t)ch * NPTS + n0;
        for (int p = lane; p < 1024; p += 32)
            atomicMax(&s[cl[p] * CH + ch], f2o(row[p]));
    }
    __syncthreads();
    for (int i = tid; i < CC * CH; i += 256) {
        const int c = i / CH, ch = i % CH;
        atomicMax(&segout[((size_t)b * CH + ch) * CC + c], s[i]);
    }
}

// ---------------- pooling math ----------------
__global__ __launch_bounds__(256) void pool_kernel(
    const unsigned* __restrict__ segf, const unsigned* __restrict__ segc,
    float* __restrict__ cfm)
{
    const int b = blockIdx.x;
    const int tid = threadIdx.x;
    __shared__ float cm[CC][CC];
    __shared__ float inv[CC];
    __shared__ float M[CC][CC];

    for (int i = tid; i < CC * CC; i += 256) {
        const int c = i / CC, j = i % CC;
        cm[c][j] = o2f(segc[((size_t)b * CC + j) * CC + c]);
    }
    __syncthreads();
    if (tid < CC) {
        float ss = 0.f;
        for (int j = 0; j < CC; j++) ss += cm[tid][j] * cm[tid][j];
        inv[tid] = 1.f / fmaxf(sqrtf(ss), 1e-12f);
    }
    __syncthreads();
    for (int i = tid; i < CC * CC; i += 256) {
        const int c1 = i / CC, c2 = i % CC;
        float ss = 0.f;
        for (int j = 0; j < CC; j++) ss += cm[c1][j] * cm[c2][j];
        M[c1][c2] = ss * inv[c1] * inv[c2];
    }
    __syncthreads();
    for (int i = tid; i < 128 * CC; i += 256) {
        const int ch = i / CC, c2 = i % CC;
        const unsigned* fr = segf + ((size_t)b * 128 + ch) * CC;
        float ss = 0.f;
        for (int c1 = 0; c1 < CC; c1++) ss += o2f(fr[c1]) * M[c1][c2];
        cfm[((size_t)b * 128 + ch) * CC + c2] = ss;
    }
}

// ---------------- gather pooled values into concat channels 128..255 ----------------
__global__ __launch_bounds__(256) void gather_kernel(
    const float* __restrict__ cfm, const int* __restrict__ idx,
    float* __restrict__ outA)
{
    __shared__ float cfs[128 * CC];
    const int tid = threadIdx.x;
    const int b = blockIdx.y;
    const int n0 = blockIdx.x * 1024;
    for (int i = tid; i < 128 * CC; i += 256) cfs[i] = cfm[(size_t)b * 128 * CC + i];
    __syncthreads();
    for (int j = tid; j < 1024; j += 256) {
        const int n = n0 + j;
        const int c = idx[(size_t)b * NPTS + n];
        float* dst = outA + ((size_t)b * 256 + 128) * NPTS + n;
        #pragma unroll 4
        for (int ch = 0; ch < 128; ch++)
            dst[(size_t)ch * NPTS] = cfs[ch * CC + c];
    }
}

// ---------------- row max ----------------
__global__ __launch_bounds__(256) void rowmax_kernel(const float* __restrict__ in, float* __restrict__ net)
{
    const int ch = blockIdx.x, b = blockIdx.y, tid = threadIdx.x;
    const float* row = in + ((size_t)b * 128 + ch) * NPTS;
    float m = -1e30f;
    for (int n = tid; n < NPTS; n += 256) m = fmaxf(m, row[n]);
    __shared__ float s[256];
    s[tid] = m;
    __syncthreads();
    for (int off = 128; off; off >>= 1) {
        if (tid < off) s[tid] = fmaxf(s[tid], s[tid + off]);
        __syncthreads();
    }
    if (tid == 0) net[b * 128 + ch] = s[0];
}

// ---------------- head MLP ----------------
__global__ __launch_bounds__(256) void mlp_kernel(
    const float* __restrict__ net,
    const float* __restrict__ dw1, const float* __restrict__ db1,
    const float* __restrict__ dw2, const float* __restrict__ db2,
    const float* __restrict__ dw3, const float* __restrict__ db3,
    float* __restrict__ out)
{
    const int tid = threadIdx.x;
    __shared__ float ns[BB][128];
    __shared__ float h1[BB][256];
    __shared__ float h2[BB][256];
    for (int i = tid; i < BB * 128; i += 256) ns[i / 128][i % 128] = net[i];
    __syncthreads();
    {
        const int j = tid;
        for (int b = 0; b < BB; b++) {
            float acc = db1[j];
            for (int i = 0; i < 128; i++) acc = fmaf(ns[b][i], dw1[i * 256 + j], acc);
            h1[b][j] = (acc >= 0.f) ? acc : 0.2f * acc;
        }
    }
    __syncthreads();
    {
        const int j = tid;
        for (int b = 0; b < BB; b++) {
            float acc = db2[j];
            for (int i = 0; i < 256; i++) acc = fmaf(h1[b][i], dw2[i * 256 + j], acc);
            h2[b][j] = (acc >= 0.f) ? acc : 0.2f * acc;
        }
    }
    __syncthreads();
    if (tid < NCAT) {
        for (int b = 0; b < BB; b++) {
            float acc = db3[tid];
            for (int i = 0; i < 256; i++) acc = fmaf(h2[b][i], dw3[i * NCAT + tid], acc);
            out[b * NCAT + tid] = acc;
        }
    }
}

// ---------------- host launcher ----------------
extern "C" void kernel_launch(void* const* d_in, const int* in_sizes, int n_in,
                              void* d_out, int out_size)
{
    const float* features = (const float*)d_in[0];
    const int*   clusters = (const int*)d_in[1];
    const float* w_in  = (const float*)d_in[2];
    const float* b_in  = (const float*)d_in[3];
    const float* w1    = (const float*)d_in[4];
    const float* b1    = (const float*)d_in[5];
    const float* w2    = (const float*)d_in[6];
    const float* b2    = (const float*)d_in[7];
    const float* w3    = (const float*)d_in[8];
    const float* b3    = (const float*)d_in[9];
    const float* wc1   = (const float*)d_in[10];
    const float* bc1   = (const float*)d_in[11];
    const float* wc2   = (const float*)d_in[12];
    const float* bc2   = (const float*)d_in[13];
    const float* wc3   = (const float*)d_in[14];
    const float* bc3   = (const float*)d_in[15];
    const float* w_out1 = (const float*)d_in[16];
    const float* b_out1 = (const float*)d_in[17];
    const float* w_out2 = (const float*)d_in[18];
    const float* b_out2 = (const float*)d_in[19];
    const float* dw1 = (const float*)d_in[20];
    const float* db1 = (const float*)d_in[21];
    const float* dw2 = (const float*)d_in[22];
    const float* db2 = (const float*)d_in[23];
    const float* dw3 = (const float*)d_in[24];
    const float* db3 = (const float*)d_in[25];
    float* out = (float*)d_out;

    float *bufA, *buf64, *FB, *bufT, *bufC, *cfm, *net, *wp;
    unsigned *segf, *segc;
    cudaGetSymbolAddress((void**)&bufA, g_bufA);
    cudaGetSymbolAddress((void**)&buf64, g_buf64);
    cudaGetSymbolAddress((void**)&FB, g_FB);
    cudaGetSymbolAddress((void**)&bufT, g_bufT);
    cudaGetSymbolAddress((void**)&bufC, g_bufC);
    cudaGetSymbolAddress((void**)&wp, g_wpack);
    cudaGetSymbolAddress((void**)&segf, g_segf);
    cudaGetSymbolAddress((void**)&segc, g_segc);
    cudaGetSymbolAddress((void**)&cfm, g_cfm);
    cudaGetSymbolAddress((void**)&net, g_net);

    const size_t S256 = (size_t)256 * NPTS, S128 = (size_t)128 * NPTS;
    const size_t S64 = (size_t)64 * NPTS, S32 = (size_t)32 * NPTS;
    const unsigned NEG = 0x3D37FFFFu;

    // packed-weight arena offsets (float units)
    const size_t OFF_W1 = 0;           // 2 x 16384
    const size_t OFF_W2 = 32768;       // 2 x  8192
    const size_t OFF_W3 = 49152;       // 2 x 16384
    const size_t OFF_WC1 = 81920;      // 2 x 16384
    const size_t OFF_WC2 = 114688;     // 2 x 32768
    const size_t OFF_WC3 = 180224;     // 2 x  8192
    const size_t OFF_WO1 = 196608;     //     32768
    const size_t OFF_WO2 = 229376;     //     16384

    // launches 1-5: packs needed first + input (so ncu -s 5 profiles conv1)
    pack_kernel<<<(64 * 256 + 255) / 256, 256>>>(w1, wp + OFF_W1, 64, 256);
    pack_kernel<<<(128 * 64 + 255) / 256, 256>>>(w2, wp + OFF_W2, 128, 64);
    pack_kernel<<<(128 * 128 + 255) / 256, 256>>>(wc1, wp + OFF_WC1, 128, 128);
    pack_kernel<<<(256 * 128 + 255) / 256, 256>>>(wc2, wp + OFF_WC2, 256, 128);
    input_kernel<<<dim3(NPTS / 128, BB), 256>>>(features, w_in, b_in, bufA);

    // launch 6 (profiled): the big Cin=256 conv
    conv5_kernel<64, 8, 256><<<dim3(NPTS / 256, 1, BB), 256>>>(bufA, S256, wp + OFF_W1, b1, buf64, S64, 256, 64);

    // remaining packs
    pack_kernel<<<(32 * 256 + 255) / 256, 256>>>(wc3, wp + OFF_WC3, 32, 256);
    pack_kernel<<<(128 * 128 + 255) / 256, 256>>>(w3, wp + OFF_W3, 128, 128);
    pack_kernel<<<(64 * 256 + 255) / 256, 256>>>(w1 + (size_t)64 * 256, wp + OFF_W1 + 16384, 64, 256);
    pack_kernel<<<(128 * 64 + 255) / 256, 256>>>(w2 + (size_t)128 * 64, wp + OFF_W2 + 8192, 128, 64);
    pack_kernel<<<(128 * 128 + 255) / 256, 256>>>(wc1 + (size_t)128 * 128, wp + OFF_WC1 + 16384, 128, 128);
    pack_kernel<<<(256 * 128 + 255) / 256, 256>>>(wc2 + (size_t)256 * 128, wp + OFF_WC2 + 32768, 256, 128);
    pack_kernel<<<(32 * 256 + 255) / 256, 256>>>(wc3 + (size_t)32 * 256, wp + OFF_WC3 + 8192, 32, 256);
    pack_kernel<<<(128 * 128 + 255) / 256, 256>>>(w3 + (size_t)128 * 128, wp + OFF_W3 + 16384, 128, 128);
    pack_kernel<<<(128 * 256 + 255) / 256, 256>>>(w_out1, wp + OFF_WO1, 128, 256);
    pack_kernel<<<(128 * 128 + 255) / 256, 256>>>(w_out2, wp + OFF_WO2, 128, 128);

    for (int i = 0; i < NBLK; i++) {
        const float* b1i = b1 + i * 64;
        const float* b2i = b2 + i * 128;
        const float* b3i = b3 + i * 128;
        const float* bc1i = bc1 + i * 128;
        const float* bc2i = bc2 + i * 256;
        const float* bc3i = bc3 + i * 32;
        const int* idxi = clusters + (size_t)i * BB * NPTS;

        if (i != 0)
            conv5_kernel<64, 8, 256><<<dim3(NPTS / 256, 1, BB), 256>>>(bufA, S256, wp + OFF_W1 + i * 16384, b1i, buf64, S64, 256, 64);
        conv5_kernel<128, 8, 128><<<dim3(NPTS / 128, 1, BB), 256>>>(buf64, S64, wp + OFF_W2 + i * 8192, b2i, FB, S128, 64, 128);
        conv5_kernel<128, 8, 128><<<dim3(NPTS / 128, 1, BB), 256>>>(FB, S128, wp + OFF_WC1 + i * 16384, bc1i, bufT, S128, 128, 128);
        conv5_kernel<128, 8, 128><<<dim3(NPTS / 128, 2, BB), 256>>>(bufT, S128, wp + OFF_WC2 + i * 32768, bc2i, bufA, S256, 128, 256);
        conv5_kernel<32, 4, 256><<<dim3(NPTS / 256, 1, BB), 256>>>(bufA, S256, wp + OFF_WC3 + i * 8192, bc3i, bufC, S32, 256, 32);

        fill_kernel<<<(BB * 128 * CC + 255) / 256, 256>>>(segf, NEG, BB * 128 * CC);
        fill_kernel<<<(BB * 32 * CC + 255) / 256, 256>>>(segc, NEG, BB * 32 * CC);
        segmax_kernel<<<dim3(NPTS / 1024, BB), 256>>>(FB, S128, 128, idxi, segf);
        segmax_kernel<<<dim3(NPTS / 1024, BB), 256>>>(bufC, S32, 32, idxi, segc);
        pool_kernel<<<BB, 256>>>(segf, segc, cfm);

        conv5_kernel<128, 8, 128><<<dim3(NPTS / 128, 1, BB), 256>>>(FB, S128, wp + OFF_W3 + i * 16384, b3i, bufA, S256, 128, 128);
        gather_kernel<<<dim3(NPTS / 1024, BB), 256>>>(cfm, idxi, bufA);
    }

    conv5_kernel<128, 8, 128><<<dim3(NPTS / 128, 1, BB), 256>>>(bufA, S256, wp + OFF_WO1, b_out1, bufT, S128, 256, 128);
    conv5_kernel<128, 8, 128><<<dim3(NPTS / 128, 1, BB), 256>>>(bufT, S128, wp + OFF_WO2, b_out2, FB, S128, 128, 128);
    rowmax_kernel<<<dim3(128, BB), 256>>>(FB, net);
    mlp_kernel<<<1, 256>>>(net, dw1, db1, dw2, db2, dw3, db3, out);
}